// round 13
// baseline (speedup 1.0000x reference)
#include <cuda_runtime.h>
#include <cuda_bf16.h>
#include <math.h>
#include <stdint.h>

#define N_NODES 50000
#define N_EDGES 1600000
#define N_GRAPHS 512
#define FDIM 128
#define NHEADS 4

// ---------------- scratch (device globals; no allocation allowed) ----------
// g_deg/g_total: zero-init at module load; re-zeroed at END of each launch
// (k_div_clean) so every replay starts clean.
__device__ __align__(16) float g_h[N_NODES * FDIM];
__device__ __align__(16) float g_x[N_NODES * FDIM];
__device__ __align__(16) float g_as[N_NODES * NHEADS];
__device__ __align__(16) float g_ad[N_NODES * NHEADS];
__device__ int g_deg[N_NODES];
__device__ int g_off[N_NODES];
__device__ int g_cur[N_NODES];
__device__ int g_srcs[N_EDGES];
__device__ int g_total;
__device__ float g_cnt[N_GRAPHS];

__device__ __forceinline__ float leaky(float v) { return v > 0.f ? v : 0.2f * v; }

__device__ __forceinline__ int detect_i64(const int* __restrict__ w) {
    int any = 0;
#pragma unroll
    for (int j = 1; j < 128; j += 2) any |= w[j];
    return (any == 0) ? 1 : 0;
}

__device__ __forceinline__ int load_idx2(const void* p, int i, int i64) {
    return i64 ? (int)((const long long*)p)[i] : ((const int*)p)[i];
}

// ---------------------------------------------------------------------------
// K1: destination-degree histogram
// ---------------------------------------------------------------------------
__global__ void k_hist(const void* __restrict__ ei) {
    __shared__ int si64;
    if (threadIdx.x == 0) si64 = detect_i64((const int*)ei);
    __syncthreads();
    const int i64 = si64;
    int e = blockIdx.x * blockDim.x + threadIdx.x;
    if (e < N_EDGES) {
        int d = load_idx2(ei, N_EDGES + e, i64);
        if ((unsigned)d < N_NODES) atomicAdd(&g_deg[d], 1);
    }
}

// ---------------------------------------------------------------------------
// K2: single-kernel scan, unordered block placement (segments disjoint only)
// ---------------------------------------------------------------------------
__global__ void k_scan() {
    const int tid = threadIdx.x;
    const int lane = tid & 31;
    const int wid = tid >> 5;
    int i = blockIdx.x * 256 + tid;
    int d = (i < N_NODES) ? g_deg[i] : 0;

    int v = d;
#pragma unroll
    for (int o = 1; o < 32; o <<= 1) {
        int n = __shfl_up_sync(0xffffffffu, v, o);
        if (lane >= o) v += n;
    }
    __shared__ int ws[8];
    if (lane == 31) ws[wid] = v;
    __syncthreads();
    if (wid == 0) {
        int t = (lane < 8) ? ws[lane] : 0;
#pragma unroll
        for (int o = 1; o < 8; o <<= 1) {
            int n = __shfl_up_sync(0xffffffffu, t, o);
            if (lane >= o) t += n;
        }
        if (lane < 8) ws[lane] = t;
    }
    __syncthreads();
    int incl = v + (wid ? ws[wid - 1] : 0);

    __shared__ int sbase;
    if (tid == 255) sbase = atomicAdd(&g_total, incl);
    __syncthreads();
    int start = sbase + incl - d;
    if (i < N_NODES) {
        g_off[i] = start;
        g_cur[i] = start;
    }
}

// ---------------------------------------------------------------------------
// K3: scatter src ids into per-destination segments
// ---------------------------------------------------------------------------
__global__ void k_scatter(const void* __restrict__ ei) {
    __shared__ int si64;
    if (threadIdx.x == 0) si64 = detect_i64((const int*)ei);
    __syncthreads();
    const int i64 = si64;
    int e = blockIdx.x * blockDim.x + threadIdx.x;
    if (e < N_EDGES) {
        int s = load_idx2(ei, e, i64);
        int d = load_idx2(ei, N_EDGES + e, i64);
        if ((unsigned)s < N_NODES && (unsigned)d < N_NODES) {
            int pos = atomicAdd(&g_cur[d], 1);
            g_srcs[pos] = s;
        }
    }
}

// ---------------------------------------------------------------------------
// K4: tiled GEMM, f32x2 FMA, MOV-free mainloop.
//     64 rows x 128 cols per block, 8r x 4c per thread.  Accumulators hold
//     COLUMN pairs; w pairs come directly from one ld.shared.v2.u64 and the
//     x tile is stored PRE-DUPLICATED ({x,x} float2): 5 LDS + 16 FFMA2
//     per k per thread.  K split into 2 staged halves (65KB smem, 3 CTA/SM).
//     XSTR2 = 66 (EVEN): row stride 528B = 33*16 keeps every v2.u64 address
//     16B-aligned (65 broke this -> misaligned address).  x reads are warp-
//     broadcast so no bank-conflict padding is needed.
// ---------------------------------------------------------------------------
#define XSTR2 66  // float2 stride; 528B rows, 16B-aligned for all k
#define SW_BYTES (64 * 128 * 4)                        // 32768
#define GEMM_SMEM_BYTES (SW_BYTES + 64 * XSTR2 * 8)    // 66560

__global__ void __launch_bounds__(256, 3)
k_gemm(const float* __restrict__ xin_opt, const float* __restrict__ W,
       const float* __restrict__ a_s, const float* __restrict__ a_d) {
    extern __shared__ float smem[];
    float* sW = smem;                          // [64 kk][128 c]
    float2* sXd = (float2*)(smem + 64 * 128);  // [64 kk][XSTR2 r] dup pairs
    const float* xin = xin_opt ? xin_opt : g_x;
    const int tid = threadIdx.x;
    const int row0 = blockIdx.x * 64;

    const int lane = tid & 31;  // col slot: cols lane*4 .. +4
    const int rs = tid >> 5;    // row slot (warp): rows rs*8 .. +8

    uint32_t sbase = (uint32_t)__cvta_generic_to_shared(smem);
    uint32_t wA = sbase + lane * 16;             // + kk*512
    uint32_t xA = sbase + SW_BYTES + rs * 64;    // + kk*528

    unsigned long long acc[8][2];  // [row][colpair]
#pragma unroll
    for (int r = 0; r < 8; r++) {
        acc[r][0] = 0ull;
        acc[r][1] = 0ull;
    }

#pragma unroll
    for (int kh = 0; kh < 2; kh++) {
        if (kh) __syncthreads();  // all warps done reading previous stage
        // stage W rows [kh*64, +64): 2048 float4, 8 per thread
        {
            const float4* Wv = (const float4*)W + kh * 64 * 32;
            float4* sWv = (float4*)sW;
#pragma unroll
            for (int i = 0; i < 8; i++) sWv[tid + 256 * i] = Wv[tid + 256 * i];
        }
        // stage x DUPLICATED: sXd[kk][r] = {x[row0+r][k], same}
#pragma unroll
        for (int i = 0; i < 4; i++) {
            int r = (tid & 31) + 32 * (i & 1);
            int k4l = (tid >> 5) + 8 * (i >> 1);  // 0..15
            int row = row0 + r;
            float4 v = (row < N_NODES)
                           ? ((const float4*)xin)[row * 32 + kh * 16 + k4l]
                           : make_float4(0.f, 0.f, 0.f, 0.f);
            sXd[(k4l * 4 + 0) * XSTR2 + r] = make_float2(v.x, v.x);
            sXd[(k4l * 4 + 1) * XSTR2 + r] = make_float2(v.y, v.y);
            sXd[(k4l * 4 + 2) * XSTR2 + r] = make_float2(v.z, v.z);
            sXd[(k4l * 4 + 3) * XSTR2 + r] = make_float2(v.w, v.w);
        }
        __syncthreads();

#pragma unroll 8
        for (int k = 0; k < 64; k++) {
            unsigned long long wd[2];
            asm("ld.shared.v2.u64 {%0,%1}, [%2];"
                : "=l"(wd[0]), "=l"(wd[1])
                : "r"(wA + (uint32_t)(k * 512)));
            unsigned long long xd[8];
            asm("ld.shared.v2.u64 {%0,%1}, [%2];"
                : "=l"(xd[0]), "=l"(xd[1])
                : "r"(xA + (uint32_t)(k * (XSTR2 * 8))));
            asm("ld.shared.v2.u64 {%0,%1}, [%2];"
                : "=l"(xd[2]), "=l"(xd[3])
                : "r"(xA + (uint32_t)(k * (XSTR2 * 8) + 16)));
            asm("ld.shared.v2.u64 {%0,%1}, [%2];"
                : "=l"(xd[4]), "=l"(xd[5])
                : "r"(xA + (uint32_t)(k * (XSTR2 * 8) + 32)));
            asm("ld.shared.v2.u64 {%0,%1}, [%2];"
                : "=l"(xd[6]), "=l"(xd[7])
                : "r"(xA + (uint32_t)(k * (XSTR2 * 8) + 48)));
#pragma unroll
            for (int r = 0; r < 8; r++) {
                asm("fma.rn.f32x2 %0, %1, %2, %0;"
                    : "+l"(acc[r][0]) : "l"(xd[r]), "l"(wd[0]));
                asm("fma.rn.f32x2 %0, %1, %2, %0;"
                    : "+l"(acc[r][1]) : "l"(xd[r]), "l"(wd[1]));
            }
        }
    }

    // unpack: acc[r][cp] = {col 2cp, col 2cp+1}
    float vals[8][4];
#pragma unroll
    for (int r = 0; r < 8; r++) {
        asm("mov.b64 {%0,%1}, %2;"
            : "=f"(vals[r][0]), "=f"(vals[r][1]) : "l"(acc[r][0]));
        asm("mov.b64 {%0,%1}, %2;"
            : "=f"(vals[r][2]), "=f"(vals[r][3]) : "l"(acc[r][1]));
    }

    const float4 asv = ((const float4*)a_s)[lane];
    const float4 adv = ((const float4*)a_d)[lane];
#pragma unroll
    for (int r = 0; r < 8; r++) {
        int row = row0 + rs * 8 + r;
        if (row >= N_NODES) break;
        float4 h = make_float4(vals[r][0], vals[r][1], vals[r][2], vals[r][3]);
        ((float4*)g_h)[row * 32 + lane] = h;
        float ps = h.x * asv.x + h.y * asv.y + h.z * asv.z + h.w * asv.w;
        float pd = h.x * adv.x + h.y * adv.y + h.z * adv.z + h.w * adv.w;
#pragma unroll
        for (int o = 4; o; o >>= 1) {
            ps += __shfl_xor_sync(0xffffffffu, ps, o);
            pd += __shfl_xor_sync(0xffffffffu, pd, o);
        }
        if ((lane & 7) == 0) {
            g_as[row * NHEADS + (lane >> 3)] = ps;
            g_ad[row * NHEADS + (lane >> 3)] = pd;
        }
    }
}

// ---------------------------------------------------------------------------
// K5: gather-based GAT aggregation + finalize (R4-measured inner loop).
// ---------------------------------------------------------------------------
__global__ void __launch_bounds__(256) k_gat(const float* __restrict__ bias) {
    const int lane = threadIdx.x & 31;
    const int head = lane >> 3;
    const int h4 = lane & 3;
    const int warp = (blockIdx.x * blockDim.x + threadIdx.x) >> 5;
    const int nwarps = (gridDim.x * blockDim.x) >> 5;
    const float4 b4 = ((const float4*)bias)[lane];

    for (int row = warp; row < N_NODES; row += nwarps) {
        float ad_h = g_ad[row * NHEADS + h4];
        float as_self = g_as[row * NHEADS + h4];
        float wself = __expf(leaky(as_self + ad_h));
        float denp = (lane < 4) ? wself : 0.f;

        float ws = __shfl_sync(0xffffffffu, wself, head);
        float4 hs = ((const float4*)g_h)[row * 32 + lane];
        float4 acc = make_float4(ws * hs.x, ws * hs.y, ws * hs.z, ws * hs.w);

        const int start = g_off[row];
        const int end = start + g_deg[row];
        for (int base = start; base < end; base += 8) {
            int idx = base + (lane >> 2);
            bool valid = idx < end;
            int s = valid ? g_srcs[idx] : 0;
            float wl = valid ? __expf(leaky(g_as[s * NHEADS + h4] + ad_h)) : 0.f;
            denp += wl;
#pragma unroll
            for (int e = 0; e < 8; e++) {
                float w = __shfl_sync(0xffffffffu, wl, e * 4 + head);
                int se = __shfl_sync(0xffffffffu, s, e * 4);
                if (w != 0.f) {
                    float4 hv = ((const float4*)g_h)[se * 32 + lane];
                    acc.x = fmaf(w, hv.x, acc.x);
                    acc.y = fmaf(w, hv.y, acc.y);
                    acc.z = fmaf(w, hv.z, acc.z);
                    acc.w = fmaf(w, hv.w, acc.w);
                }
            }
        }
#pragma unroll
        for (int o = 4; o < 32; o <<= 1)
            denp += __shfl_xor_sync(0xffffffffu, denp, o);
        float den = __shfl_sync(0xffffffffu, denp, head) + 1e-16f;
        float inv = __fdividef(1.0f, den);
        float4 r;
        r.x = acc.x * inv + b4.x;
        r.y = acc.y * inv + b4.y;
        r.z = acc.z * inv + b4.z;
        r.w = acc.w * inv + b4.w;
        r.x = r.x > 0.f ? r.x : expm1f(r.x);
        r.y = r.y > 0.f ? r.y : expm1f(r.y);
        r.z = r.z > 0.f ? r.z : expm1f(r.z);
        r.w = r.w > 0.f ? r.w : expm1f(r.w);
        ((float4*)g_x)[row * 32 + lane] = r;
    }
}

// ---------------------------------------------------------------------------
// Pooling
// ---------------------------------------------------------------------------
__global__ void k_zero(float* __restrict__ out) {
    int i = blockIdx.x * blockDim.x + threadIdx.x;
    if (i < N_GRAPHS * FDIM) out[i] = 0.f;
    if (i < N_GRAPHS) g_cnt[i] = 0.f;
}

__global__ void k_pool(const void* __restrict__ batch,
                       const void* __restrict__ ei,
                       float* __restrict__ out) {
    __shared__ int si64;
    if (threadIdx.x == 0) si64 = detect_i64((const int*)ei);
    __syncthreads();
    const int i64 = si64;
    const int lane = threadIdx.x & 31;
    const int warp = (blockIdx.x * blockDim.x + threadIdx.x) >> 5;
    const int nwarps = (gridDim.x * blockDim.x) >> 5;
    for (int row = warp; row < N_NODES; row += nwarps) {
        int g = load_idx2(batch, row, i64);
        if ((unsigned)g >= N_GRAPHS) continue;
        float4 v = ((const float4*)g_x)[row * 32 + lane];
        float* p = out + g * FDIM + lane * 4;
        asm volatile("red.global.add.v4.f32 [%0], {%1,%2,%3,%4};" ::"l"(p),
                     "f"(v.x), "f"(v.y), "f"(v.z), "f"(v.w)
                     : "memory");
        if (lane == 0) {
            float* pc = g_cnt + g;
            asm volatile("red.global.add.f32 [%0], %1;" ::"l"(pc), "f"(1.0f)
                         : "memory");
        }
    }
}

__global__ void k_div_clean(float* __restrict__ out) {
    int i = blockIdx.x * blockDim.x + threadIdx.x;
    if (i < N_GRAPHS * FDIM) {
        float c = g_cnt[i >> 7];
        out[i] = out[i] / fmaxf(c, 1.0f);
    }
    if (i < N_NODES) g_deg[i] = 0;
    if (i == 0) g_total = 0;
}

// ---------------------------------------------------------------------------
extern "C" void kernel_launch(void* const* d_in, const int* in_sizes, int n_in,
                              void* d_out, int out_size) {
    const float* x = (const float*)d_in[0];
    const float* Ws = (const float*)d_in[1];
    const float* att_src = (const float*)d_in[2];
    const float* att_dst = (const float*)d_in[3];
    const float* biases = (const float*)d_in[4];
    const void* ei = d_in[5];
    const void* batch = d_in[6];
    float* out = (float*)d_out;

    cudaFuncSetAttribute(k_gemm, cudaFuncAttributeMaxDynamicSharedMemorySize,
                         GEMM_SMEM_BYTES);

    const int EBLK = (N_EDGES + 255) / 256;
    const int NODEBLK = (N_NODES + 255) / 256;
    const int GATBLK = (N_NODES + 7) / 8;
    const int GEMMBLK = (N_NODES + 63) / 64;  // 782

    // Launch #4 gets profiled: k_gemm layer 0 -> verify fma/issue delta.
    k_hist<<<EBLK, 256>>>(ei);     // 1
    k_scan<<<NODEBLK, 256>>>();    // 2
    k_scatter<<<EBLK, 256>>>(ei);  // 3

    for (int l = 0; l < 3; l++) {
        const float* xin = (l == 0) ? x : nullptr;
        k_gemm<<<GEMMBLK, 256, GEMM_SMEM_BYTES>>>(                 // 4, 6, 8
            xin, Ws + l * FDIM * FDIM, att_src + l * NHEADS * 32,
            att_dst + l * NHEADS * 32);
        k_gat<<<GATBLK, 256>>>(biases + l * FDIM);                 // 5, 7, 9
    }
    k_zero<<<(N_GRAPHS * FDIM + 255) / 256, 256>>>(out);
    k_pool<<<1184, 256>>>(batch, ei, out);
    k_div_clean<<<256, 256>>>(out);
}

// round 14
// speedup vs baseline: 1.1528x; 1.1528x over previous
#include <cuda_runtime.h>
#include <cuda_bf16.h>
#include <math.h>
#include <stdint.h>

#define N_NODES 50000
#define N_EDGES 1600000
#define N_GRAPHS 512
#define FDIM 128
#define NHEADS 4

// ---------------- scratch (device globals; no allocation allowed) ----------
// g_deg/g_total: zero-init at module load; re-zeroed at END of each launch
// (k_div_clean) so every replay starts clean.
__device__ __align__(16) float g_h[N_NODES * FDIM];
__device__ __align__(16) float g_x[N_NODES * FDIM];
__device__ __align__(16) float g_as[N_NODES * NHEADS];
__device__ __align__(16) float g_ad[N_NODES * NHEADS];
__device__ int g_deg[N_NODES];
__device__ int g_off[N_NODES];
__device__ int g_cur[N_NODES];
__device__ int g_srcs[N_EDGES];
__device__ int g_total;
__device__ float g_cnt[N_GRAPHS];

__device__ __forceinline__ float leaky(float v) { return v > 0.f ? v : 0.2f * v; }

__device__ __forceinline__ int detect_i64(const int* __restrict__ w) {
    int any = 0;
#pragma unroll
    for (int j = 1; j < 128; j += 2) any |= w[j];
    return (any == 0) ? 1 : 0;
}

__device__ __forceinline__ int load_idx2(const void* p, int i, int i64) {
    return i64 ? (int)((const long long*)p)[i] : ((const int*)p)[i];
}

// ---------------------------------------------------------------------------
// K2: single-kernel scan, unordered block placement (segments disjoint only)
// ---------------------------------------------------------------------------
__global__ void k_scan() {
    const int tid = threadIdx.x;
    const int lane = tid & 31;
    const int wid = tid >> 5;
    int i = blockIdx.x * 256 + tid;
    int d = (i < N_NODES) ? g_deg[i] : 0;

    int v = d;
#pragma unroll
    for (int o = 1; o < 32; o <<= 1) {
        int n = __shfl_up_sync(0xffffffffu, v, o);
        if (lane >= o) v += n;
    }
    __shared__ int ws[8];
    if (lane == 31) ws[wid] = v;
    __syncthreads();
    if (wid == 0) {
        int t = (lane < 8) ? ws[lane] : 0;
#pragma unroll
        for (int o = 1; o < 8; o <<= 1) {
            int n = __shfl_up_sync(0xffffffffu, t, o);
            if (lane >= o) t += n;
        }
        if (lane < 8) ws[lane] = t;
    }
    __syncthreads();
    int incl = v + (wid ? ws[wid - 1] : 0);

    __shared__ int sbase;
    if (tid == 255) sbase = atomicAdd(&g_total, incl);
    __syncthreads();
    int start = sbase + incl - d;
    if (i < N_NODES) {
        g_off[i] = start;
        g_cur[i] = start;
    }
}

// ---------------------------------------------------------------------------
// K3: scatter src ids into per-destination segments
// ---------------------------------------------------------------------------
__global__ void k_scatter(const void* __restrict__ ei) {
    __shared__ int si64;
    if (threadIdx.x == 0) si64 = detect_i64((const int*)ei);
    __syncthreads();
    const int i64 = si64;
    int e = blockIdx.x * blockDim.x + threadIdx.x;
    if (e < N_EDGES) {
        int s = load_idx2(ei, e, i64);
        int d = load_idx2(ei, N_EDGES + e, i64);
        if ((unsigned)s < N_NODES && (unsigned)d < N_NODES) {
            int pos = atomicAdd(&g_cur[d], 1);
            g_srcs[pos] = s;
        }
    }
}

// ---------------------------------------------------------------------------
// K4: tiled GEMM (R10-measured mainloop: row-pair f32x2 acc, split-k staged,
//     3 CTA/SM).  Layer 0 additionally runs the destination-degree histogram
//     (grid-stride over edges) after the epilogue — hides k_hist behind the
//     GEMM (DRAM idle there) and shifts k_gat to profiled launch #4.
// ---------------------------------------------------------------------------
#define XSTRIDE 68  // floats; k*XSTRIDE*4 = 272k = 17k*16 -> 16B aligned
#define SW_BYTES (64 * 128 * 4)                        // 32768
#define GEMM_SMEM_BYTES (SW_BYTES + 64 * XSTRIDE * 4)  // 50176

__global__ void __launch_bounds__(256, 3)
k_gemm(const float* __restrict__ xin_opt, const float* __restrict__ W,
       const float* __restrict__ a_s, const float* __restrict__ a_d,
       const void* __restrict__ ei, int do_hist) {
    extern __shared__ float smem[];
    float* sW = smem;             // [64 kk][128 c]
    float* sX = smem + 64 * 128;  // [64 kk][XSTRIDE r] transposed
    const float* xin = xin_opt ? xin_opt : g_x;
    const int tid = threadIdx.x;
    const int row0 = blockIdx.x * 64;

    const int lane = tid & 31;  // col slot: cols lane*4 .. +4
    const int rs = tid >> 5;    // row slot (warp): rows rs*8 .. +8

    uint32_t sbase = (uint32_t)__cvta_generic_to_shared(smem);
    uint32_t wA = sbase + lane * 16;             // + kk*512
    uint32_t xA = sbase + SW_BYTES + rs * 32;    // + kk*XSTRIDE*4

    unsigned long long acc[4][4];
#pragma unroll
    for (int p = 0; p < 4; p++)
#pragma unroll
        for (int c = 0; c < 4; c++) acc[p][c] = 0ull;

#pragma unroll
    for (int kh = 0; kh < 2; kh++) {
        if (kh) __syncthreads();  // all warps done reading previous stage
        {
            const float4* Wv = (const float4*)W + kh * 64 * 32;
            float4* sWv = (float4*)sW;
#pragma unroll
            for (int i = 0; i < 8; i++) sWv[tid + 256 * i] = Wv[tid + 256 * i];
        }
#pragma unroll
        for (int i = 0; i < 4; i++) {
            int r = (tid & 31) + 32 * (i & 1);
            int k4l = (tid >> 5) + 8 * (i >> 1);  // 0..15
            int row = row0 + r;
            float4 v = (row < N_NODES)
                           ? ((const float4*)xin)[row * 32 + kh * 16 + k4l]
                           : make_float4(0.f, 0.f, 0.f, 0.f);
            sX[(k4l * 4 + 0) * XSTRIDE + r] = v.x;
            sX[(k4l * 4 + 1) * XSTRIDE + r] = v.y;
            sX[(k4l * 4 + 2) * XSTRIDE + r] = v.z;
            sX[(k4l * 4 + 3) * XSTRIDE + r] = v.w;
        }
        __syncthreads();

#pragma unroll 8
        for (int k = 0; k < 64; k++) {
            float w0, w1, w2, w3;
            asm("ld.shared.v4.f32 {%0,%1,%2,%3}, [%4];"
                : "=f"(w0), "=f"(w1), "=f"(w2), "=f"(w3)
                : "r"(wA + (uint32_t)(k * 512)));
            unsigned long long wd[4];
            asm("mov.b64 %0, {%1,%1};" : "=l"(wd[0]) : "f"(w0));
            asm("mov.b64 %0, {%1,%1};" : "=l"(wd[1]) : "f"(w1));
            asm("mov.b64 %0, {%1,%1};" : "=l"(wd[2]) : "f"(w2));
            asm("mov.b64 %0, {%1,%1};" : "=l"(wd[3]) : "f"(w3));
            unsigned long long xp[4];
            asm("ld.shared.v2.u64 {%0,%1}, [%2];"
                : "=l"(xp[0]), "=l"(xp[1])
                : "r"(xA + (uint32_t)(k * XSTRIDE * 4)));
            asm("ld.shared.v2.u64 {%0,%1}, [%2];"
                : "=l"(xp[2]), "=l"(xp[3])
                : "r"(xA + (uint32_t)(k * XSTRIDE * 4 + 16)));
#pragma unroll
            for (int p = 0; p < 4; p++)
#pragma unroll
                for (int c = 0; c < 4; c++)
                    asm("fma.rn.f32x2 %0, %1, %2, %0;"
                        : "+l"(acc[p][c]) : "l"(xp[p]), "l"(wd[c]));
        }
    }

    // unpack: rows 2p (lo) and 2p+1 (hi)
    float vals[8][4];
#pragma unroll
    for (int p = 0; p < 4; p++)
#pragma unroll
        for (int c = 0; c < 4; c++) {
            float lo, hi;
            asm("mov.b64 {%0,%1}, %2;" : "=f"(lo), "=f"(hi) : "l"(acc[p][c]));
            vals[2 * p][c] = lo;
            vals[2 * p + 1][c] = hi;
        }

    const float4 asv = ((const float4*)a_s)[lane];
    const float4 adv = ((const float4*)a_d)[lane];
#pragma unroll
    for (int r = 0; r < 8; r++) {
        int row = row0 + rs * 8 + r;
        if (row >= N_NODES) break;
        float4 h = make_float4(vals[r][0], vals[r][1], vals[r][2], vals[r][3]);
        ((float4*)g_h)[row * 32 + lane] = h;
        float ps = h.x * asv.x + h.y * asv.y + h.z * asv.z + h.w * asv.w;
        float pd = h.x * adv.x + h.y * adv.y + h.z * adv.z + h.w * adv.w;
#pragma unroll
        for (int o = 4; o; o >>= 1) {
            ps += __shfl_xor_sync(0xffffffffu, ps, o);
            pd += __shfl_xor_sync(0xffffffffu, pd, o);
        }
        if ((lane & 7) == 0) {
            g_as[row * NHEADS + (lane >> 3)] = ps;
            g_ad[row * NHEADS + (lane >> 3)] = pd;
        }
    }

    // Fused degree histogram (layer 0 only): overlaps edge DRAM reads +
    // L2 atomics behind the next blocks' GEMM compute.
    if (do_hist) {
        __shared__ int si64;
        if (tid == 0) si64 = detect_i64((const int*)ei);
        __syncthreads();
        const int i64 = si64;
        const int nth = gridDim.x * blockDim.x;
        for (int e = blockIdx.x * blockDim.x + tid; e < N_EDGES; e += nth) {
            int d = load_idx2(ei, N_EDGES + e, i64);
            if ((unsigned)d < N_NODES) atomicAdd(&g_deg[d], 1);
        }
    }
}

// ---------------------------------------------------------------------------
// K5: gather-based GAT aggregation + finalize (R4-measured inner loop).
// ---------------------------------------------------------------------------
__global__ void __launch_bounds__(256) k_gat(const float* __restrict__ bias) {
    const int lane = threadIdx.x & 31;
    const int head = lane >> 3;
    const int h4 = lane & 3;
    const int warp = (blockIdx.x * blockDim.x + threadIdx.x) >> 5;
    const int nwarps = (gridDim.x * blockDim.x) >> 5;
    const float4 b4 = ((const float4*)bias)[lane];

    for (int row = warp; row < N_NODES; row += nwarps) {
        float ad_h = g_ad[row * NHEADS + h4];
        float as_self = g_as[row * NHEADS + h4];
        float wself = __expf(leaky(as_self + ad_h));
        float denp = (lane < 4) ? wself : 0.f;

        float ws = __shfl_sync(0xffffffffu, wself, head);
        float4 hs = ((const float4*)g_h)[row * 32 + lane];
        float4 acc = make_float4(ws * hs.x, ws * hs.y, ws * hs.z, ws * hs.w);

        const int start = g_off[row];
        const int end = start + g_deg[row];
        for (int base = start; base < end; base += 8) {
            int idx = base + (lane >> 2);
            bool valid = idx < end;
            int s = valid ? g_srcs[idx] : 0;
            float wl = valid ? __expf(leaky(g_as[s * NHEADS + h4] + ad_h)) : 0.f;
            denp += wl;
#pragma unroll
            for (int e = 0; e < 8; e++) {
                float w = __shfl_sync(0xffffffffu, wl, e * 4 + head);
                int se = __shfl_sync(0xffffffffu, s, e * 4);
                if (w != 0.f) {
                    float4 hv = ((const float4*)g_h)[se * 32 + lane];
                    acc.x = fmaf(w, hv.x, acc.x);
                    acc.y = fmaf(w, hv.y, acc.y);
                    acc.z = fmaf(w, hv.z, acc.z);
                    acc.w = fmaf(w, hv.w, acc.w);
                }
            }
        }
#pragma unroll
        for (int o = 4; o < 32; o <<= 1)
            denp += __shfl_xor_sync(0xffffffffu, denp, o);
        float den = __shfl_sync(0xffffffffu, denp, head) + 1e-16f;
        float inv = __fdividef(1.0f, den);
        float4 r;
        r.x = acc.x * inv + b4.x;
        r.y = acc.y * inv + b4.y;
        r.z = acc.z * inv + b4.z;
        r.w = acc.w * inv + b4.w;
        r.x = r.x > 0.f ? r.x : expm1f(r.x);
        r.y = r.y > 0.f ? r.y : expm1f(r.y);
        r.z = r.z > 0.f ? r.z : expm1f(r.z);
        r.w = r.w > 0.f ? r.w : expm1f(r.w);
        ((float4*)g_x)[row * 32 + lane] = r;
    }
}

// ---------------------------------------------------------------------------
// Pooling
// ---------------------------------------------------------------------------
__global__ void k_zero(float* __restrict__ out) {
    int i = blockIdx.x * blockDim.x + threadIdx.x;
    if (i < N_GRAPHS * FDIM) out[i] = 0.f;
    if (i < N_GRAPHS) g_cnt[i] = 0.f;
}

__global__ void k_pool(const void* __restrict__ batch,
                       const void* __restrict__ ei,
                       float* __restrict__ out) {
    __shared__ int si64;
    if (threadIdx.x == 0) si64 = detect_i64((const int*)ei);
    __syncthreads();
    const int i64 = si64;
    const int lane = threadIdx.x & 31;
    const int warp = (blockIdx.x * blockDim.x + threadIdx.x) >> 5;
    const int nwarps = (gridDim.x * blockDim.x) >> 5;
    for (int row = warp; row < N_NODES; row += nwarps) {
        int g = load_idx2(batch, row, i64);
        if ((unsigned)g >= N_GRAPHS) continue;
        float4 v = ((const float4*)g_x)[row * 32 + lane];
        float* p = out + g * FDIM + lane * 4;
        asm volatile("red.global.add.v4.f32 [%0], {%1,%2,%3,%4};" ::"l"(p),
                     "f"(v.x), "f"(v.y), "f"(v.z), "f"(v.w)
                     : "memory");
        if (lane == 0) {
            float* pc = g_cnt + g;
            asm volatile("red.global.add.f32 [%0], %1;" ::"l"(pc), "f"(1.0f)
                         : "memory");
        }
    }
}

__global__ void k_div_clean(float* __restrict__ out) {
    int i = blockIdx.x * blockDim.x + threadIdx.x;
    if (i < N_GRAPHS * FDIM) {
        float c = g_cnt[i >> 7];
        out[i] = out[i] / fmaxf(c, 1.0f);
    }
    if (i < N_NODES) g_deg[i] = 0;
    if (i == 0) g_total = 0;
}

// ---------------------------------------------------------------------------
extern "C" void kernel_launch(void* const* d_in, const int* in_sizes, int n_in,
                              void* d_out, int out_size) {
    const float* x = (const float*)d_in[0];
    const float* Ws = (const float*)d_in[1];
    const float* att_src = (const float*)d_in[2];
    const float* att_dst = (const float*)d_in[3];
    const float* biases = (const float*)d_in[4];
    const void* ei = d_in[5];
    const void* batch = d_in[6];
    float* out = (float*)d_out;

    cudaFuncSetAttribute(k_gemm, cudaFuncAttributeMaxDynamicSharedMemorySize,
                         GEMM_SMEM_BYTES);

    const int EBLK = (N_EDGES + 255) / 256;
    const int NODEBLK = (N_NODES + 255) / 256;
    const int GATBLK = (N_NODES + 7) / 8;
    const int GEMMBLK = (N_NODES + 63) / 64;  // 782

    // Launch order: gemm0(+hist)=1, scan=2, scatter=3, gat0=4 (PROFILED).
    k_gemm<<<GEMMBLK, 256, GEMM_SMEM_BYTES>>>(x, Ws, att_src, att_dst, ei, 1);
    k_scan<<<NODEBLK, 256>>>();
    k_scatter<<<EBLK, 256>>>(ei);
    k_gat<<<GATBLK, 256>>>(biases);

    for (int l = 1; l < 3; l++) {
        k_gemm<<<GEMMBLK, 256, GEMM_SMEM_BYTES>>>(
            nullptr, Ws + l * FDIM * FDIM, att_src + l * NHEADS * 32,
            att_dst + l * NHEADS * 32, ei, 0);
        k_gat<<<GATBLK, 256>>>(biases + l * FDIM);
    }
    k_zero<<<(N_GRAPHS * FDIM + 255) / 256, 256>>>(out);
    k_pool<<<1184, 256>>>(batch, ei, out);
    k_div_clean<<<256, 256>>>(out);
}